// round 1
// baseline (speedup 1.0000x reference)
#include <cuda_runtime.h>

// Problem constants (fixed by the dataset)
#define NI 6
#define CC 64
#define HI 224
#define WI 400
#define DD 8
#define HH 128
#define WW 128
#define PP (DD*HH*WW)          // 131072 voxels
#define VOXEL 0.4f

// NHWC-staged images: 6*224*400*64 floats = 137.6 MB (device bss, allowed)
__device__ float g_img[(size_t)NI*HI*WI*CC];
// Folded camera matrices: per cam, M = K@R (9) and T = K@t (3)
__device__ float g_cam[NI*12];

// ---------------------------------------------------------------------------
// Kernel 1: fold intrinsics/rotation/translation into a single 3x4 per camera
// ---------------------------------------------------------------------------
__global__ void cam_setup_kernel(const float* __restrict__ K,
                                 const float* __restrict__ R,
                                 const float* __restrict__ T) {
    int n = threadIdx.x;
    if (n >= NI) return;
    const float* k = K + n*9;
    const float* r = R + n*9;
    const float* t = T + n*3;
    float* m = g_cam + n*12;
    #pragma unroll
    for (int i = 0; i < 3; i++) {
        #pragma unroll
        for (int j = 0; j < 3; j++) {
            m[i*3+j] = k[i*3+0]*r[0*3+j] + k[i*3+1]*r[1*3+j] + k[i*3+2]*r[2*3+j];
        }
        m[9+i] = k[i*3+0]*t[0] + k[i*3+1]*t[1] + k[i*3+2]*t[2];
    }
}

// ---------------------------------------------------------------------------
// Kernel 2: NCHW -> NHWC transpose of the images (smem-tiled, both sides
// coalesced). Tile = 32 channels x 32 width positions.
// ---------------------------------------------------------------------------
__global__ __launch_bounds__(256) void nchw_to_nhwc_kernel(const float* __restrict__ in) {
    __shared__ float tile[32][33];
    int wt = blockIdx.x;            // width tile: 0..12
    int h  = blockIdx.y;            // 0..223
    int nz = blockIdx.z;            // 0..11 : n*2 + ctile
    int n  = nz >> 1;
    int c0 = (nz & 1) << 5;
    int w0 = wt << 5;
    int tx = threadIdx.x;           // 0..31
    int ty = threadIdx.y;           // 0..7

    #pragma unroll
    for (int i = 0; i < 4; i++) {
        int c = c0 + ty + 8*i;
        int w = w0 + tx;
        float v = 0.0f;
        if (w < WI) v = in[(((size_t)n*CC + c)*HI + h)*WI + w];
        tile[ty + 8*i][tx] = v;
    }
    __syncthreads();
    #pragma unroll
    for (int i = 0; i < 4; i++) {
        int w = w0 + ty + 8*i;
        int c = c0 + tx;
        if (w < WI) g_img[(((size_t)n*HI + h)*WI + w)*CC + c] = tile[tx][ty + 8*i];
    }
}

// ---------------------------------------------------------------------------
// Kernel 3: main projection+sampling.
// Warp per voxel; lane L owns channels {2L, 2L+1} (float2 gathers, each
// corner fetch is one coalesced 256B warp request). 8 warps/block, smem
// transpose stage for coalesced (C, P) output writes.
// ---------------------------------------------------------------------------
__device__ __forceinline__ float2 samp2(int base_nhw, int cb, bool valid) {
    if (!valid) return make_float2(0.0f, 0.0f);
    const float2* p = reinterpret_cast<const float2*>(g_img + ((size_t)base_nhw*CC + cb));
    return __ldg(p);
}

__global__ __launch_bounds__(256) void project_kernel(float* __restrict__ out) {
    __shared__ float cams[NI*12];
    __shared__ float st[CC][8];

    int tid = threadIdx.x;
    if (tid < NI*12) cams[tid] = g_cam[tid];
    __syncthreads();

    int warp = tid >> 5;
    int lane = tid & 31;
    int p = blockIdx.x * 8 + warp;

    // flat point index p corresponds to (h, w, d) with d fastest
    int h = p >> 10;            // p / (W*D) = p / 1024
    int w = (p >> 3) & 127;     // (p / D) % W
    int d = p & 7;              // p % D

    float px = ((float)h - (HH - 1) * 0.5f) * VOXEL;
    float py = ((float)w - (WW - 1) * 0.5f) * VOXEL;
    float pz = ((float)d - (DD - 1) * 0.5f) * VOXEL;

    float accx = 0.0f, accy = 0.0f;
    int cb = lane * 2;

    #pragma unroll
    for (int n = 0; n < NI; n++) {
        const float* m = cams + n*12;
        float X = m[0]*px + m[1]*py + m[2]*pz + m[9];
        float Y = m[3]*px + m[4]*py + m[5]*pz + m[10];
        float Z = m[6]*px + m[7]*py + m[8]*pz + m[11];
        if (Z < 0.1f) continue;     // masked -> contributes 0

        float invZ = 1.0f / Z;
        float u = X * invZ;
        float v = Y * invZ;

        // replicate reference's grid_sample-style coordinate mangling
        float xs = v * ((float)WI / (float)(HI - 1)) - 0.5f;
        float ys = u * ((float)HI / (float)(WI - 1)) - 0.5f;
        xs = fminf(fmaxf(xs, -10.0f), (float)WI + 10.0f);
        ys = fminf(fmaxf(ys, -10.0f), (float)HI + 10.0f);

        float x0f = floorf(xs);
        float y0f = floorf(ys);
        float wx = xs - x0f;
        float wy = ys - y0f;
        int x0 = (int)x0f;
        int y0 = (int)y0f;
        int x1 = x0 + 1;
        int y1 = y0 + 1;

        bool vx0 = (x0 >= 0) && (x0 < WI);
        bool vx1 = (x1 >= 0) && (x1 < WI);
        bool vy0 = (y0 >= 0) && (y0 < HI);
        bool vy1 = (y1 >= 0) && (y1 < HI);

        int row0 = (n*HI + y0)*WI;
        int row1 = (n*HI + y1)*WI;

        float2 v00 = samp2(row0 + x0, cb, vx0 && vy0);
        float2 v10 = samp2(row0 + x1, cb, vx1 && vy0);
        float2 v01 = samp2(row1 + x0, cb, vx0 && vy1);
        float2 v11 = samp2(row1 + x1, cb, vx1 && vy1);

        float w00 = (1.0f - wx) * (1.0f - wy);
        float w10 = wx * (1.0f - wy);
        float w01 = (1.0f - wx) * wy;
        float w11 = wx * wy;

        accx += w00*v00.x + w10*v10.x + w01*v01.x + w11*v11.x;
        accy += w00*v00.y + w10*v10.y + w01*v01.y + w11*v11.y;
    }

    const float inv_n = 1.0f / (float)NI;
    st[cb][warp]     = accx * inv_n;
    st[cb + 1][warp] = accy * inv_n;
    __syncthreads();

    // coalesced-ish write-out: out[c*P + p_base + j]
    int p_base = blockIdx.x * 8;
    #pragma unroll
    for (int k = tid; k < CC*8; k += 256) {
        int c = k >> 3;
        int j = k & 7;
        out[(size_t)c * PP + p_base + j] = st[c][j];
    }
}

// ---------------------------------------------------------------------------
extern "C" void kernel_launch(void* const* d_in, const int* in_sizes, int n_in,
                              void* d_out, int out_size) {
    const float* images      = (const float*)d_in[0];
    const float* intrinsic   = (const float*)d_in[1];
    const float* rotation    = (const float*)d_in[2];
    const float* translation = (const float*)d_in[3];
    float* out = (float*)d_out;

    cam_setup_kernel<<<1, 32>>>(intrinsic, rotation, translation);

    dim3 tb(32, 8);
    dim3 tg((WI + 31) / 32, HI, NI * 2);
    nchw_to_nhwc_kernel<<<tg, tb>>>(images);

    project_kernel<<<PP / 8, 256>>>(out);
}

// round 2
// speedup vs baseline: 1.0375x; 1.0375x over previous
#include <cuda_runtime.h>
#include <cuda_fp16.h>

// Problem constants (fixed by the dataset)
#define NI 6
#define CC 64
#define HI 224
#define WI 400
#define DD 8
#define HH 128
#define WW 128
#define PP (DD*HH*WW)          // 131072 voxels
#define VOXEL 0.4f

// NHWC-staged images in fp16: 6*224*400*64*2B = 68.8 MB (device bss, allowed)
__device__ __half g_img[(size_t)NI*HI*WI*CC];
// Folded camera matrices: per cam, M = K@R (9) and T = K@t (3)
__device__ float g_cam[NI*12];

// ---------------------------------------------------------------------------
// Kernel 1: fold intrinsics/rotation/translation into a single 3x4 per camera
// ---------------------------------------------------------------------------
__global__ void cam_setup_kernel(const float* __restrict__ K,
                                 const float* __restrict__ R,
                                 const float* __restrict__ T) {
    int n = threadIdx.x;
    if (n >= NI) return;
    const float* k = K + n*9;
    const float* r = R + n*9;
    const float* t = T + n*3;
    float* m = g_cam + n*12;
    #pragma unroll
    for (int i = 0; i < 3; i++) {
        #pragma unroll
        for (int j = 0; j < 3; j++) {
            m[i*3+j] = k[i*3+0]*r[0*3+j] + k[i*3+1]*r[1*3+j] + k[i*3+2]*r[2*3+j];
        }
        m[9+i] = k[i*3+0]*t[0] + k[i*3+1]*t[1] + k[i*3+2]*t[2];
    }
}

// ---------------------------------------------------------------------------
// Kernel 2: NCHW fp32 -> NHWC fp16 transpose (smem-tiled, both sides
// coalesced). Tile = 32 channels x 32 width positions.
// ---------------------------------------------------------------------------
__global__ __launch_bounds__(256) void nchw_to_nhwc_kernel(const float* __restrict__ in) {
    __shared__ float tile[32][33];
    int wt = blockIdx.x;            // width tile: 0..12
    int h  = blockIdx.y;            // 0..223
    int nz = blockIdx.z;            // 0..11 : n*2 + ctile
    int n  = nz >> 1;
    int c0 = (nz & 1) << 5;
    int w0 = wt << 5;
    int tx = threadIdx.x;           // 0..31
    int ty = threadIdx.y;           // 0..7
    int tid = ty * 32 + tx;

    #pragma unroll
    for (int i = 0; i < 4; i++) {
        int c = c0 + ty + 8*i;
        int w = w0 + tx;
        float v = 0.0f;
        if (w < WI) v = in[(((size_t)n*CC + c)*HI + h)*WI + w];
        tile[ty + 8*i][tx] = v;
    }
    __syncthreads();
    // write phase: each thread emits one half2 (channel pair) per iteration.
    // idx -> (w_in_tile = idx>>4, cpair = idx&15); contiguous 4B stores across
    // the 16-thread cpair groups -> 64B runs per pixel.
    #pragma unroll
    for (int it = 0; it < 2; it++) {
        int idx = it * 256 + tid;
        int wl = idx >> 4;          // 0..31
        int cp = idx & 15;          // 0..15 -> channels c0+2cp, c0+2cp+1
        int w = w0 + wl;
        if (w < WI) {
            __half2 hv = __floats2half2_rn(tile[2*cp][wl], tile[2*cp+1][wl]);
            __half2* dst = reinterpret_cast<__half2*>(
                g_img + ((((size_t)n*HI + h)*WI + w)*CC + c0 + 2*cp));
            *dst = hv;
        }
    }
}

// ---------------------------------------------------------------------------
// Kernel 3: main projection+sampling.
// Warp per voxel; lane L owns channels {2L, 2L+1} (half2 gathers -> each
// corner fetch is one coalesced 128B warp request). 8 warps/block, smem
// transpose stage for coalesced (C, P) output writes.
// ---------------------------------------------------------------------------
__device__ __forceinline__ float2 samp2(int base_nhw, int cb, bool valid) {
    if (!valid) return make_float2(0.0f, 0.0f);
    const __half2* p = reinterpret_cast<const __half2*>(g_img + ((size_t)base_nhw*CC + cb));
    return __half22float2(__ldg(p));
}

__global__ __launch_bounds__(256) void project_kernel(float* __restrict__ out) {
    __shared__ float cams[NI*12];
    __shared__ float st[CC][8];

    int tid = threadIdx.x;
    if (tid < NI*12) cams[tid] = g_cam[tid];
    __syncthreads();

    int warp = tid >> 5;
    int lane = tid & 31;
    int p = blockIdx.x * 8 + warp;

    // flat point index p corresponds to (h, w, d) with d fastest
    int h = p >> 10;            // p / (W*D)
    int w = (p >> 3) & 127;     // (p / D) % W
    int d = p & 7;              // p % D

    float px = ((float)h - (HH - 1) * 0.5f) * VOXEL;
    float py = ((float)w - (WW - 1) * 0.5f) * VOXEL;
    float pz = ((float)d - (DD - 1) * 0.5f) * VOXEL;

    float accx = 0.0f, accy = 0.0f;
    int cb = lane * 2;

    #pragma unroll
    for (int n = 0; n < NI; n++) {
        const float* m = cams + n*12;
        float X = m[0]*px + m[1]*py + m[2]*pz + m[9];
        float Y = m[3]*px + m[4]*py + m[5]*pz + m[10];
        float Z = m[6]*px + m[7]*py + m[8]*pz + m[11];
        if (Z < 0.1f) continue;     // masked -> contributes 0

        float invZ = 1.0f / Z;
        float u = X * invZ;
        float v = Y * invZ;

        // grid_sample-style coordinate mangling (matches reference algebra)
        float xs = v * ((float)WI / (float)(HI - 1)) - 0.5f;
        float ys = u * ((float)HI / (float)(WI - 1)) - 0.5f;
        xs = fminf(fmaxf(xs, -10.0f), (float)WI + 10.0f);
        ys = fminf(fmaxf(ys, -10.0f), (float)HI + 10.0f);

        float x0f = floorf(xs);
        float y0f = floorf(ys);
        float wx = xs - x0f;
        float wy = ys - y0f;
        int x0 = (int)x0f;
        int y0 = (int)y0f;
        int x1 = x0 + 1;
        int y1 = y0 + 1;

        bool vx0 = (x0 >= 0) && (x0 < WI);
        bool vx1 = (x1 >= 0) && (x1 < WI);
        bool vy0 = (y0 >= 0) && (y0 < HI);
        bool vy1 = (y1 >= 0) && (y1 < HI);

        int row0 = (n*HI + y0)*WI;
        int row1 = (n*HI + y1)*WI;

        float2 v00 = samp2(row0 + x0, cb, vx0 && vy0);
        float2 v10 = samp2(row0 + x1, cb, vx1 && vy0);
        float2 v01 = samp2(row1 + x0, cb, vx0 && vy1);
        float2 v11 = samp2(row1 + x1, cb, vx1 && vy1);

        float w00 = (1.0f - wx) * (1.0f - wy);
        float w10 = wx * (1.0f - wy);
        float w01 = (1.0f - wx) * wy;
        float w11 = wx * wy;

        accx += w00*v00.x + w10*v10.x + w01*v01.x + w11*v11.x;
        accy += w00*v00.y + w10*v10.y + w01*v01.y + w11*v11.y;
    }

    const float inv_n = 1.0f / (float)NI;
    st[cb][warp]     = accx * inv_n;
    st[cb + 1][warp] = accy * inv_n;
    __syncthreads();

    // coalesced write-out: out[c*P + p_base + j], 32B runs per channel
    int p_base = blockIdx.x * 8;
    #pragma unroll
    for (int k = tid; k < CC*8; k += 256) {
        int c = k >> 3;
        int j = k & 7;
        out[(size_t)c * PP + p_base + j] = st[c][j];
    }
}

// ---------------------------------------------------------------------------
extern "C" void kernel_launch(void* const* d_in, const int* in_sizes, int n_in,
                              void* d_out, int out_size) {
    const float* images      = (const float*)d_in[0];
    const float* intrinsic   = (const float*)d_in[1];
    const float* rotation    = (const float*)d_in[2];
    const float* translation = (const float*)d_in[3];
    float* out = (float*)d_out;

    cam_setup_kernel<<<1, 32>>>(intrinsic, rotation, translation);

    dim3 tb(32, 8);
    dim3 tg((WI + 31) / 32, HI, NI * 2);
    nchw_to_nhwc_kernel<<<tg, tb>>>(images);

    project_kernel<<<PP / 8, 256>>>(out);
}

// round 3
// speedup vs baseline: 1.5102x; 1.4556x over previous
#include <cuda_runtime.h>
#include <cuda_fp16.h>

// Problem constants (fixed by the dataset)
#define NI 6
#define CC 64
#define HI 224
#define WI 400
#define DD 8
#define HH 128
#define WW 128
#define PP (DD*HH*WW)          // 131072 voxels
#define VOXEL 0.4f

// NHWC-staged images in fp16: 6*224*400*64*2B = 68.8 MB (device bss, allowed)
__device__ __align__(256) __half g_img[(size_t)NI*HI*WI*CC];

// ---------------------------------------------------------------------------
// Kernel 1: NCHW fp32 -> NHWC fp16 transpose (smem-tiled, both sides
// coalesced). Tile = 32 channels x 32 width positions.
// ---------------------------------------------------------------------------
__global__ __launch_bounds__(256) void nchw_to_nhwc_kernel(const float* __restrict__ in) {
    __shared__ float tile[32][33];
    int wt = blockIdx.x;            // width tile: 0..12
    int h  = blockIdx.y;            // 0..223
    int nz = blockIdx.z;            // 0..11 : n*2 + ctile
    int n  = nz >> 1;
    int c0 = (nz & 1) << 5;
    int w0 = wt << 5;
    int tx = threadIdx.x;           // 0..31
    int ty = threadIdx.y;           // 0..7
    int tid = ty * 32 + tx;

    #pragma unroll
    for (int i = 0; i < 4; i++) {
        int c = c0 + ty + 8*i;
        int w = w0 + tx;
        float v = 0.0f;
        if (w < WI) v = in[(((size_t)n*CC + c)*HI + h)*WI + w];
        tile[ty + 8*i][tx] = v;
    }
    __syncthreads();
    // write phase: thread -> pixel (tid>>3), channel quad (tid&7): one 8B store
    {
        int wl = tid >> 3;          // 0..31
        int q  = tid & 7;           // channels c0+4q .. c0+4q+3
        int w = w0 + wl;
        if (w < WI) {
            __half2 lo = __floats2half2_rn(tile[4*q + 0][wl], tile[4*q + 1][wl]);
            __half2 hi = __floats2half2_rn(tile[4*q + 2][wl], tile[4*q + 3][wl]);
            uint2 val;
            val.x = *reinterpret_cast<unsigned*>(&lo);
            val.y = *reinterpret_cast<unsigned*>(&hi);
            uint2* dst = reinterpret_cast<uint2*>(
                g_img + ((((size_t)n*HI + h)*WI + w)*CC + c0 + 4*q));
            *dst = val;
        }
    }
}

// ---------------------------------------------------------------------------
// Kernel 2: projection+sampling.
// Warp = 4 voxels (consecutive d). 8 lanes per voxel, lane owns 8 channels:
// each bilinear corner fetch is one LDG.128 (16B/lane, 128B per voxel-group).
// Camera matrices folded in-block. smem-staged (C, P) output, 128B runs.
// ---------------------------------------------------------------------------
__device__ __forceinline__ void acc4(float acc[8], uint4 q, float w) {
    unsigned v[4] = {q.x, q.y, q.z, q.w};
    #pragma unroll
    for (int j = 0; j < 4; j++) {
        __half2 h = *reinterpret_cast<__half2*>(&v[j]);
        float2 f = __half22float2(h);
        acc[2*j]   += w * f.x;
        acc[2*j+1] += w * f.y;
    }
}

__global__ __launch_bounds__(256) void project_kernel(const float* __restrict__ K,
                                                      const float* __restrict__ R,
                                                      const float* __restrict__ T,
                                                      float* __restrict__ out) {
    __shared__ float cams[NI*12];
    __shared__ float st[CC][33];   // padded: only cols 0..31 used

    int tid = threadIdx.x;
    // fold K@R (9) and K@t (3) per camera, 72 values
    if (tid < NI*12) {
        int n = tid / 12;
        int j = tid - n*12;
        const float* k = K + n*9;
        float val;
        if (j < 9) {
            int i = j / 3, c = j - 3*i;
            val = k[i*3+0]*__ldg(R + n*9 + 0 + c)
                + k[i*3+1]*__ldg(R + n*9 + 3 + c)
                + k[i*3+2]*__ldg(R + n*9 + 6 + c);
        } else {
            int i = j - 9;
            val = k[i*3+0]*__ldg(T + n*3 + 0)
                + k[i*3+1]*__ldg(T + n*3 + 1)
                + k[i*3+2]*__ldg(T + n*3 + 2);
        }
        cams[tid] = val;
    }
    __syncthreads();

    int warp = tid >> 5;
    int lane = tid & 31;
    int vsel = lane >> 3;          // 0..3 : voxel within warp
    int cb   = (lane & 7) * 8;     // channel base (8 channels per lane)

    int p = blockIdx.x * 32 + warp * 4 + vsel;

    // flat point index p -> (h, w, d), d fastest
    int h = p >> 10;
    int w = (p >> 3) & 127;
    int d = p & 7;

    float px = ((float)h - (HH - 1) * 0.5f) * VOXEL;
    float py = ((float)w - (WW - 1) * 0.5f) * VOXEL;
    float pz = ((float)d - (DD - 1) * 0.5f) * VOXEL;

    float acc[8];
    #pragma unroll
    for (int j = 0; j < 8; j++) acc[j] = 0.0f;

    const uint4 zero4 = make_uint4(0u, 0u, 0u, 0u);

    #pragma unroll
    for (int n = 0; n < NI; n++) {
        const float* m = cams + n*12;
        float X = m[0]*px + m[1]*py + m[2]*pz + m[9];
        float Y = m[3]*px + m[4]*py + m[5]*pz + m[10];
        float Z = m[6]*px + m[7]*py + m[8]*pz + m[11];
        if (Z < 0.1f) continue;     // masked -> contributes 0

        float invZ = 1.0f / Z;
        float u = X * invZ;
        float v = Y * invZ;

        // grid_sample-style coordinate mangling (matches reference algebra)
        float xs = v * ((float)WI / (float)(HI - 1)) - 0.5f;
        float ys = u * ((float)HI / (float)(WI - 1)) - 0.5f;
        xs = fminf(fmaxf(xs, -10.0f), (float)WI + 10.0f);
        ys = fminf(fmaxf(ys, -10.0f), (float)HI + 10.0f);

        float x0f = floorf(xs);
        float y0f = floorf(ys);
        float wx = xs - x0f;
        float wy = ys - y0f;
        int x0 = (int)x0f;
        int y0 = (int)y0f;
        int x1 = x0 + 1;
        int y1 = y0 + 1;

        bool vx0 = (x0 >= 0) && (x0 < WI);
        bool vx1 = (x1 >= 0) && (x1 < WI);
        bool vy0 = (y0 >= 0) && (y0 < HI);
        bool vy1 = (y1 >= 0) && (y1 < HI);

        int row0 = (n*HI + y0)*WI;
        int row1 = (n*HI + y1)*WI;

        const __half* base = g_img + cb;
        const uint4* p00 = reinterpret_cast<const uint4*>(base + (size_t)(row0 + x0)*CC);
        const uint4* p10 = reinterpret_cast<const uint4*>(base + (size_t)(row0 + x1)*CC);
        const uint4* p01 = reinterpret_cast<const uint4*>(base + (size_t)(row1 + x0)*CC);
        const uint4* p11 = reinterpret_cast<const uint4*>(base + (size_t)(row1 + x1)*CC);

        uint4 q00 = (vx0 && vy0) ? __ldg(p00) : zero4;
        uint4 q10 = (vx1 && vy0) ? __ldg(p10) : zero4;
        uint4 q01 = (vx0 && vy1) ? __ldg(p01) : zero4;
        uint4 q11 = (vx1 && vy1) ? __ldg(p11) : zero4;

        float w00 = (1.0f - wx) * (1.0f - wy);
        float w10 = wx * (1.0f - wy);
        float w01 = (1.0f - wx) * wy;
        float w11 = wx * wy;

        acc4(acc, q00, w00);
        acc4(acc, q10, w10);
        acc4(acc, q01, w01);
        acc4(acc, q11, w11);
    }

    const float inv_n = 1.0f / (float)NI;
    int vcol = warp * 4 + vsel;    // 0..31
    #pragma unroll
    for (int j = 0; j < 8; j++) st[cb + j][vcol] = acc[j] * inv_n;
    __syncthreads();

    // coalesced write-out: out[c*PP + p_base + j], 128B runs per channel
    int p_base = blockIdx.x * 32;
    #pragma unroll
    for (int k = tid; k < CC*32; k += 256) {
        int c = k >> 5;
        int j = k & 31;
        out[(size_t)c * PP + p_base + j] = st[c][j];
    }
}

// ---------------------------------------------------------------------------
extern "C" void kernel_launch(void* const* d_in, const int* in_sizes, int n_in,
                              void* d_out, int out_size) {
    const float* images      = (const float*)d_in[0];
    const float* intrinsic   = (const float*)d_in[1];
    const float* rotation    = (const float*)d_in[2];
    const float* translation = (const float*)d_in[3];
    float* out = (float*)d_out;

    dim3 tb(32, 8);
    dim3 tg((WI + 31) / 32, HI, NI * 2);
    nchw_to_nhwc_kernel<<<tg, tb>>>(images);

    project_kernel<<<PP / 32, 256>>>(intrinsic, rotation, translation, out);
}

// round 4
// speedup vs baseline: 1.8707x; 1.2388x over previous
#include <cuda_runtime.h>
#include <cuda_fp16.h>

// Problem constants (fixed by the dataset)
#define NI 6
#define CC 64
#define HI 224
#define WI 400
#define DD 8
#define HH 128
#define WW 128
#define PP (DD*HH*WW)          // 131072 voxels
#define VOXEL 0.4f

// NHWC-staged images in fp16: 6*224*400*64*2B = 68.8 MB (device bss, allowed)
__device__ __align__(256) __half g_img[(size_t)NI*HI*WI*CC];

// ---------------------------------------------------------------------------
// Kernel 1: NCHW fp32 -> NHWC fp16 transpose.
// Block = all 64 channels x 32 width positions at one (n, h).
// Read: 128B coalesced rows. Write: one 16B STG per thread; 8 threads form a
// full 128B pixel line; warp covers 4 consecutive pixels = 512B contiguous.
// ---------------------------------------------------------------------------
__global__ __launch_bounds__(256) void nchw_to_nhwc_kernel(const float* __restrict__ in) {
    __shared__ float tile[64][33];
    int w0 = blockIdx.x << 5;       // width tile base: 0,32,...,384
    int h  = blockIdx.y;            // 0..223
    int n  = blockIdx.z;            // 0..5
    int tid = threadIdx.x;
    int tx = tid & 31;              // width lane
    int ty = tid >> 5;              // 0..7

    const float* src = in + ((size_t)n*CC*HI + h)*WI;
    int w = w0 + tx;
    bool inw = (w < WI);
    #pragma unroll
    for (int i = 0; i < 8; i++) {
        int c = ty*8 + i;
        tile[c][tx] = inw ? __ldg(src + (size_t)c*HI*WI + w) : 0.0f;
    }
    __syncthreads();

    // thread -> (pixel = tid>>3, quad = tid&7): one 16B store (8 channels)
    int pix = tid >> 3;             // 0..31
    int q   = tid & 7;              // channel quad base 8q? no: 8 quads of 8ch
    int wp = w0 + pix;
    if (wp < WI) {
        int c0 = q * 8;
        __half2 h0 = __floats2half2_rn(tile[c0+0][pix], tile[c0+1][pix]);
        __half2 h1 = __floats2half2_rn(tile[c0+2][pix], tile[c0+3][pix]);
        __half2 h2 = __floats2half2_rn(tile[c0+4][pix], tile[c0+5][pix]);
        __half2 h3 = __floats2half2_rn(tile[c0+6][pix], tile[c0+7][pix]);
        uint4 val;
        val.x = *reinterpret_cast<unsigned*>(&h0);
        val.y = *reinterpret_cast<unsigned*>(&h1);
        val.z = *reinterpret_cast<unsigned*>(&h2);
        val.w = *reinterpret_cast<unsigned*>(&h3);
        uint4* dst = reinterpret_cast<uint4*>(
            g_img + ((((size_t)n*HI + h)*WI + wp)*CC + c0));
        *dst = val;
    }
}

// ---------------------------------------------------------------------------
// Kernel 2: projection+sampling.
// Warp = 4 voxels (consecutive d). 8 lanes per voxel, lane owns 8 channels:
// each bilinear corner fetch is one LDG.128. Per-camera bilinear blend in
// HFMA2 (half2 pairs), fp32 cross-camera accumulation.
// ---------------------------------------------------------------------------
__global__ __launch_bounds__(256) void project_kernel(const float* __restrict__ K,
                                                      const float* __restrict__ R,
                                                      const float* __restrict__ T,
                                                      float* __restrict__ out) {
    __shared__ float cams[NI*12];
    __shared__ float st[CC][33];   // padded: only cols 0..31 used

    int tid = threadIdx.x;
    // fold K@R (9) and K@t (3) per camera, 72 values
    if (tid < NI*12) {
        int n = tid / 12;
        int j = tid - n*12;
        const float* k = K + n*9;
        float val;
        if (j < 9) {
            int i = j / 3, c = j - 3*i;
            val = k[i*3+0]*__ldg(R + n*9 + 0 + c)
                + k[i*3+1]*__ldg(R + n*9 + 3 + c)
                + k[i*3+2]*__ldg(R + n*9 + 6 + c);
        } else {
            int i = j - 9;
            val = k[i*3+0]*__ldg(T + n*3 + 0)
                + k[i*3+1]*__ldg(T + n*3 + 1)
                + k[i*3+2]*__ldg(T + n*3 + 2);
        }
        cams[tid] = val;
    }
    __syncthreads();

    int warp = tid >> 5;
    int lane = tid & 31;
    int vsel = lane >> 3;          // 0..3 : voxel within warp
    int cb   = (lane & 7) * 8;     // channel base (8 channels per lane)

    int p = blockIdx.x * 32 + warp * 4 + vsel;

    // flat point index p -> (h, w, d), d fastest
    int h = p >> 10;
    int w = (p >> 3) & 127;
    int d = p & 7;

    float px = ((float)h - (HH - 1) * 0.5f) * VOXEL;
    float py = ((float)w - (WW - 1) * 0.5f) * VOXEL;
    float pz = ((float)d - (DD - 1) * 0.5f) * VOXEL;

    float acc[8];
    #pragma unroll
    for (int j = 0; j < 8; j++) acc[j] = 0.0f;

    const uint4 zero4 = make_uint4(0u, 0u, 0u, 0u);

    #pragma unroll
    for (int n = 0; n < NI; n++) {
        const float* m = cams + n*12;
        float X = m[0]*px + m[1]*py + m[2]*pz + m[9];
        float Y = m[3]*px + m[4]*py + m[5]*pz + m[10];
        float Z = m[6]*px + m[7]*py + m[8]*pz + m[11];
        if (Z < 0.1f) continue;     // masked -> contributes 0

        float u = __fdividef(X, Z);
        float v = __fdividef(Y, Z);

        // grid_sample-style coordinate mangling (matches reference algebra).
        // The reference's +/-10 clamps only alter coordinates that are
        // already out-of-range (and thus masked to zero) -> safe to drop.
        float xs = v * ((float)WI / (float)(HI - 1)) - 0.5f;
        float ys = u * ((float)HI / (float)(WI - 1)) - 0.5f;

        float x0f = floorf(xs);
        float y0f = floorf(ys);
        float wx = xs - x0f;
        float wy = ys - y0f;
        int x0 = (int)x0f;
        int y0 = (int)y0f;
        int x1 = x0 + 1;
        int y1 = y0 + 1;

        bool vx0 = (x0 >= 0) && (x0 < WI);
        bool vx1 = (x1 >= 0) && (x1 < WI);
        bool vy0 = (y0 >= 0) && (y0 < HI);
        bool vy1 = (y1 >= 0) && (y1 < HI);

        int row0 = (n*HI + y0)*WI;
        int row1 = (n*HI + y1)*WI;

        const __half* base = g_img + cb;
        const uint4* p00 = reinterpret_cast<const uint4*>(base + (size_t)(row0 + x0)*CC);
        const uint4* p10 = reinterpret_cast<const uint4*>(base + (size_t)(row0 + x1)*CC);
        const uint4* p01 = reinterpret_cast<const uint4*>(base + (size_t)(row1 + x0)*CC);
        const uint4* p11 = reinterpret_cast<const uint4*>(base + (size_t)(row1 + x1)*CC);

        uint4 q00 = (vx0 && vy0) ? __ldg(p00) : zero4;
        uint4 q10 = (vx1 && vy0) ? __ldg(p10) : zero4;
        uint4 q01 = (vx0 && vy1) ? __ldg(p01) : zero4;
        uint4 q11 = (vx1 && vy1) ? __ldg(p11) : zero4;

        __half2 hw00 = __float2half2_rn((1.0f - wx) * (1.0f - wy));
        __half2 hw10 = __float2half2_rn(wx * (1.0f - wy));
        __half2 hw01 = __float2half2_rn((1.0f - wx) * wy);
        __half2 hw11 = __float2half2_rn(wx * wy);

        const __half2* a00 = reinterpret_cast<const __half2*>(&q00);
        const __half2* a10 = reinterpret_cast<const __half2*>(&q10);
        const __half2* a01 = reinterpret_cast<const __half2*>(&q01);
        const __half2* a11 = reinterpret_cast<const __half2*>(&q11);

        #pragma unroll
        for (int j = 0; j < 4; j++) {
            __half2 s = __hmul2(hw00, a00[j]);
            s = __hfma2(hw10, a10[j], s);
            s = __hfma2(hw01, a01[j], s);
            s = __hfma2(hw11, a11[j], s);
            float2 f = __half22float2(s);
            acc[2*j]   += f.x;
            acc[2*j+1] += f.y;
        }
    }

    const float inv_n = 1.0f / (float)NI;
    int vcol = warp * 4 + vsel;    // 0..31
    #pragma unroll
    for (int j = 0; j < 8; j++) st[cb + j][vcol] = acc[j] * inv_n;
    __syncthreads();

    // coalesced write-out: out[c*PP + p_base + j], 128B runs per channel
    int p_base = blockIdx.x * 32;
    #pragma unroll
    for (int k = tid; k < CC*32; k += 256) {
        int c = k >> 5;
        int j = k & 31;
        out[(size_t)c * PP + p_base + j] = st[c][j];
    }
}

// ---------------------------------------------------------------------------
extern "C" void kernel_launch(void* const* d_in, const int* in_sizes, int n_in,
                              void* d_out, int out_size) {
    const float* images      = (const float*)d_in[0];
    const float* intrinsic   = (const float*)d_in[1];
    const float* rotation    = (const float*)d_in[2];
    const float* translation = (const float*)d_in[3];
    float* out = (float*)d_out;

    dim3 tg((WI + 31) / 32, HI, NI);
    nchw_to_nhwc_kernel<<<tg, 256>>>(images);

    project_kernel<<<PP / 32, 256>>>(intrinsic, rotation, translation, out);
}

// round 5
// speedup vs baseline: 1.9916x; 1.0646x over previous
#include <cuda_runtime.h>
#include <cuda_fp16.h>

// Problem constants (fixed by the dataset)
#define NI 6
#define CC 64
#define HI 224
#define WI 400
#define DD 8
#define HH 128
#define WW 128
#define PP (DD*HH*WW)          // 131072 voxels
#define VOXEL 0.4f

#define SKIPINFO 0xFFFFFFFFu

// NHWC-staged images in fp16: 6*224*400*64*2B = 68.8 MB (device bss, allowed)
__device__ __align__(256) __half g_img[(size_t)NI*HI*WI*CC];

// ---------------------------------------------------------------------------
// Kernel 1: NCHW fp32 -> NHWC fp16 transpose (at the chip memory roofline).
// ---------------------------------------------------------------------------
__global__ __launch_bounds__(256) void nchw_to_nhwc_kernel(const float* __restrict__ in) {
    __shared__ float tile[64][33];
    int w0 = blockIdx.x << 5;       // width tile base
    int h  = blockIdx.y;            // 0..223
    int n  = blockIdx.z;            // 0..5
    int tid = threadIdx.x;
    int tx = tid & 31;
    int ty = tid >> 5;

    const float* src = in + ((size_t)n*CC*HI + h)*WI;
    int w = w0 + tx;
    bool inw = (w < WI);
    #pragma unroll
    for (int i = 0; i < 8; i++) {
        int c = ty*8 + i;
        tile[c][tx] = inw ? __ldg(src + (size_t)c*HI*WI + w) : 0.0f;
    }
    __syncthreads();

    int pix = tid >> 3;             // 0..31
    int q   = tid & 7;
    int wp = w0 + pix;
    if (wp < WI) {
        int c0 = q * 8;
        __half2 h0 = __floats2half2_rn(tile[c0+0][pix], tile[c0+1][pix]);
        __half2 h1 = __floats2half2_rn(tile[c0+2][pix], tile[c0+3][pix]);
        __half2 h2 = __floats2half2_rn(tile[c0+4][pix], tile[c0+5][pix]);
        __half2 h3 = __floats2half2_rn(tile[c0+6][pix], tile[c0+7][pix]);
        uint4 val;
        val.x = *reinterpret_cast<unsigned*>(&h0);
        val.y = *reinterpret_cast<unsigned*>(&h1);
        val.z = *reinterpret_cast<unsigned*>(&h2);
        val.w = *reinterpret_cast<unsigned*>(&h3);
        uint4* dst = reinterpret_cast<uint4*>(
            g_img + ((((size_t)n*HI + h)*WI + wp)*CC + c0));
        *dst = val;
    }
}

// ---------------------------------------------------------------------------
// packed f32x2 helpers (Blackwell add.rn.f32x2: one instr = 2 fp32 adds)
// ---------------------------------------------------------------------------
__device__ __forceinline__ unsigned long long f32x2_pack(float lo, float hi) {
    unsigned long long r;
    asm("mov.b64 %0, {%1, %2};" : "=l"(r) : "r"(__float_as_uint(lo)), "r"(__float_as_uint(hi)));
    return r;
}
__device__ __forceinline__ void f32x2_unpack(unsigned long long v, float& lo, float& hi) {
    unsigned a, b;
    asm("mov.b64 {%0, %1}, %2;" : "=r"(a), "=r"(b) : "l"(v));
    lo = __uint_as_float(a); hi = __uint_as_float(b);
}
__device__ __forceinline__ unsigned long long f32x2_add(unsigned long long a, unsigned long long b) {
    unsigned long long r;
    asm("add.rn.f32x2 %0, %1, %2;" : "=l"(r) : "l"(a), "l"(b));
    return r;
}

// ---------------------------------------------------------------------------
// Kernel 2: projection+sampling.
// Warp = 4 voxels x 8 lanes. Geometry computed ONCE per (voxel, camera) by
// lane vsel*8+c and broadcast via shfl: info word (x0:9b | y0:8b | 4 valid
// flags, SKIP sentinel for Z<0.1) + 4 bilinear weights (x 1/6) as 2 half2s.
// Each lane owns 8 channels: one LDG.128 per corner. fp32x2 accumulation.
// ---------------------------------------------------------------------------
__global__ __launch_bounds__(256) void project_kernel(const float* __restrict__ K,
                                                      const float* __restrict__ R,
                                                      const float* __restrict__ T,
                                                      float* __restrict__ out) {
    __shared__ float cams[NI*12];
    __shared__ float st[CC][33];   // padded: only cols 0..31 used

    int tid = threadIdx.x;
    // fold K@R (9) and K@t (3) per camera, 72 values
    if (tid < NI*12) {
        int n = tid / 12;
        int j = tid - n*12;
        const float* k = K + n*9;
        float val;
        if (j < 9) {
            int i = j / 3, c = j - 3*i;
            val = k[i*3+0]*__ldg(R + n*9 + 0 + c)
                + k[i*3+1]*__ldg(R + n*9 + 3 + c)
                + k[i*3+2]*__ldg(R + n*9 + 6 + c);
        } else {
            int i = j - 9;
            val = k[i*3+0]*__ldg(T + n*3 + 0)
                + k[i*3+1]*__ldg(T + n*3 + 1)
                + k[i*3+2]*__ldg(T + n*3 + 2);
        }
        cams[tid] = val;
    }
    __syncthreads();

    int warp = tid >> 5;
    int lane = tid & 31;
    int vsel = lane >> 3;          // voxel within warp
    int cb   = (lane & 7) * 8;     // channel base (8 channels per lane)

    int p = blockIdx.x * 32 + warp * 4 + vsel;
    int h = p >> 10;
    int w = (p >> 3) & 127;
    int d = p & 7;

    float px = ((float)h - (HH - 1) * 0.5f) * VOXEL;
    float py = ((float)w - (WW - 1) * 0.5f) * VOXEL;
    float pz = ((float)d - (DD - 1) * 0.5f) * VOXEL;

    // ---- geometry phase: lane = vsel*8 + c computes (own voxel, camera c) ----
    unsigned gInfo = SKIPINFO;
    unsigned gWA = 0, gWB = 0;
    {
        int c = lane & 7;
        if (c < NI) {
            const float* m = cams + c*12;
            float X = m[0]*px + m[1]*py + m[2]*pz + m[9];
            float Y = m[3]*px + m[4]*py + m[5]*pz + m[10];
            float Z = m[6]*px + m[7]*py + m[8]*pz + m[11];
            if (Z >= 0.1f) {
                float u = __fdividef(X, Z);
                float v = __fdividef(Y, Z);
                // grid_sample-style coordinate mangling (matches reference;
                // +/-10 clamps dropped: they only affect masked samples)
                float xs = v * ((float)WI / (float)(HI - 1)) - 0.5f;
                float ys = u * ((float)HI / (float)(WI - 1)) - 0.5f;
                float x0f = floorf(xs);
                float y0f = floorf(ys);
                float wx = xs - x0f;
                float wy = ys - y0f;
                int x0 = (int)x0f;
                int y0 = (int)y0f;
                unsigned f = 0;
                if (x0 >= 0   && x0 < WI && y0 >= 0   && y0 < HI) f |= 1u;   // 00
                if (x0 >= -1  && x0 < WI-1 && y0 >= 0 && y0 < HI) f |= 2u;   // 10 (x1 in range)
                if (x0 >= 0   && x0 < WI && y0 >= -1  && y0 < HI-1) f |= 4u; // 01
                if (x0 >= -1  && x0 < WI-1 && y0 >= -1 && y0 < HI-1) f |= 8u;// 11
                int x0p = min(max(x0, -1), WI-1) + 1;   // [0, WI]
                int y0p = min(max(y0, -1), HI-1) + 1;   // [0, HI]
                gInfo = (unsigned)x0p | ((unsigned)y0p << 9) | (f << 17);
                const float inv_n = 1.0f / (float)NI;
                float w00 = (1.0f - wx) * (1.0f - wy) * inv_n;
                float w10 = wx * (1.0f - wy) * inv_n;
                float w01 = (1.0f - wx) * wy * inv_n;
                float w11 = wx * wy * inv_n;
                __half2 a = __floats2half2_rn(w00, w10);
                __half2 b = __floats2half2_rn(w01, w11);
                gWA = *reinterpret_cast<unsigned*>(&a);
                gWB = *reinterpret_cast<unsigned*>(&b);
            }
        }
    }

    unsigned long long acc[4];
    #pragma unroll
    for (int j = 0; j < 4; j++) acc[j] = 0ull;

    const uint4 zero4 = make_uint4(0u, 0u, 0u, 0u);
    const __half* base = g_img + cb;
    int srcbase = lane & 24;

    #pragma unroll
    for (int n = 0; n < NI; n++) {
        unsigned info = __shfl_sync(0xFFFFFFFFu, gInfo, srcbase + n);
        unsigned wa   = __shfl_sync(0xFFFFFFFFu, gWA,   srcbase + n);
        unsigned wb   = __shfl_sync(0xFFFFFFFFu, gWB,   srcbase + n);
        if (info == SKIPINFO) continue;

        int x0p = info & 511;
        int y0p = (info >> 9) & 255;
        int x0c = max(x0p - 1, 0);
        int x1c = min(x0p, WI - 1);
        int y0c = max(y0p - 1, 0);
        int y1c = min(y0p, HI - 1);
        int r0 = n*HI*WI + y0c*WI;
        int r1 = n*HI*WI + y1c*WI;

        uint4 q00 = (info & (1u << 17)) ? __ldg(reinterpret_cast<const uint4*>(base + (size_t)(r0 + x0c)*CC)) : zero4;
        uint4 q10 = (info & (2u << 17)) ? __ldg(reinterpret_cast<const uint4*>(base + (size_t)(r0 + x1c)*CC)) : zero4;
        uint4 q01 = (info & (4u << 17)) ? __ldg(reinterpret_cast<const uint4*>(base + (size_t)(r1 + x0c)*CC)) : zero4;
        uint4 q11 = (info & (8u << 17)) ? __ldg(reinterpret_cast<const uint4*>(base + (size_t)(r1 + x1c)*CC)) : zero4;

        __half2 pa = *reinterpret_cast<__half2*>(&wa);
        __half2 pb = *reinterpret_cast<__half2*>(&wb);
        __half2 hw00 = __low2half2(pa);
        __half2 hw10 = __high2half2(pa);
        __half2 hw01 = __low2half2(pb);
        __half2 hw11 = __high2half2(pb);

        const __half2* a00 = reinterpret_cast<const __half2*>(&q00);
        const __half2* a10 = reinterpret_cast<const __half2*>(&q10);
        const __half2* a01 = reinterpret_cast<const __half2*>(&q01);
        const __half2* a11 = reinterpret_cast<const __half2*>(&q11);

        #pragma unroll
        for (int j = 0; j < 4; j++) {
            __half2 s = __hmul2(hw00, a00[j]);
            s = __hfma2(hw10, a10[j], s);
            s = __hfma2(hw01, a01[j], s);
            s = __hfma2(hw11, a11[j], s);
            float2 f = __half22float2(s);
            acc[j] = f32x2_add(acc[j], f32x2_pack(f.x, f.y));
        }
    }

    int vcol = warp * 4 + vsel;    // 0..31
    #pragma unroll
    for (int j = 0; j < 4; j++) {
        float lo, hi;
        f32x2_unpack(acc[j], lo, hi);
        st[cb + 2*j][vcol]     = lo;
        st[cb + 2*j + 1][vcol] = hi;
    }
    __syncthreads();

    // coalesced write-out: out[c*PP + p_base + j], 128B runs per channel
    int p_base = blockIdx.x * 32;
    #pragma unroll
    for (int k = tid; k < CC*32; k += 256) {
        int c = k >> 5;
        int j = k & 31;
        out[(size_t)c * PP + p_base + j] = st[c][j];
    }
}

// ---------------------------------------------------------------------------
extern "C" void kernel_launch(void* const* d_in, const int* in_sizes, int n_in,
                              void* d_out, int out_size) {
    const float* images      = (const float*)d_in[0];
    const float* intrinsic   = (const float*)d_in[1];
    const float* rotation    = (const float*)d_in[2];
    const float* translation = (const float*)d_in[3];
    float* out = (float*)d_out;

    dim3 tg((WI + 31) / 32, HI, NI);
    nchw_to_nhwc_kernel<<<tg, 256>>>(images);

    project_kernel<<<PP / 32, 256>>>(intrinsic, rotation, translation, out);
}